// round 8
// baseline (speedup 1.0000x reference)
#include <cuda_runtime.h>
#include <cuda_bf16.h>

// PeriodicConvOp == parity-scrambled 3x3 conv.
// x: [8,4,512,512] f32, weight: [32,36] f32, out: [8,8,512,512] f32.
//
// For flat channel n in [0,32): g = n>>3 (gy=g>>1, gx=g&1), o = n&7:
//   conv[n](h,w) = sum_{cin,ky,kx} W[(g*8+o)*36 + cin*9+ky*3+kx]
//                  * x[b,cin, 2h+gy+ky-1, 2w+gx+kx-1]
//   out[b, n>>2, 2h + ((n>>1)&1), 2w + (n&1)] = conv[n](h,w)
//
// 256 threads: m = tid&3 (o-pair {2m,2m+1} -> j=0/1 f32x2 lanes),
// tcx = (tid>>2)&3 (4 superpixels), ty = tid>>4 (0..15).
// Tile: 16x16 superpixels (32x32 out px) per block.
//
// Input tile stored NON-duplicated (plain f32, halves input LDS bytes);
// {v,v} FFMA2 operands built with mov.b64 at load time. Staging is
// warp-per-row, division-free.

#define PITCHF 36  // input tile row pitch in floats (rows are 34 wide)

__device__ __forceinline__ void ffma2(unsigned long long& d,
                                      unsigned long long a,
                                      unsigned long long b) {
    asm("fma.rn.f32x2 %0, %1, %2, %0;" : "+l"(d) : "l"(a), "l"(b));
}

__device__ __forceinline__ unsigned long long dup2(float v) {
    unsigned long long u;
    asm("mov.b64 %0, {%1, %1};" : "=l"(u) : "f"(v));
    return u;
}

// load 10 consecutive f32 positions (LDS.128 x2 + LDS.64), pack as {v,v}
__device__ __forceinline__ void ldrowp(unsigned long long* d, const float* p) {
    const float4 a = *(const float4*)(p);
    const float4 b = *(const float4*)(p + 4);
    const float2 c = *(const float2*)(p + 8);
    d[0] = dup2(a.x); d[1] = dup2(a.y); d[2] = dup2(a.z); d[3] = dup2(a.w);
    d[4] = dup2(b.x); d[5] = dup2(b.y); d[6] = dup2(b.z); d[7] = dup2(b.w);
    d[8] = dup2(c.x); d[9] = dup2(c.y);
}

__global__ __launch_bounds__(256, 3)
void pconv_kernel(const float* __restrict__ x, const float* __restrict__ wg,
                  float* __restrict__ out) {
    __shared__ __align__(16) float s_in[4 * 34 * PITCHF];   // ~19.6 KB
    // weights: s_w[((tap*4 + m)*4 + g)*2 + e] = W[(g*8 + 2m + e)*36 + tap]
    __shared__ __align__(16) float s_w[1152];

    const int tid  = threadIdx.x;
    const int lane = tid & 31;
    const int wid8 = tid >> 5;            // warp id 0..7
    const int b   = blockIdx.z;
    const int h0  = blockIdx.y * 16;      // superpixel row base
    const int w0  = blockIdx.x * 16;      // superpixel col base
    const int py0 = 2 * h0 - 1;           // pixel row of tile row 0
    const int px0 = 2 * w0 - 1;

    // ---- stage weights (transposed/interleaved, division-free) ----
    for (int d = tid; d < 1152; d += 256) {
        int e = d & 1, g = (d >> 1) & 3, m = (d >> 3) & 3, tap = d >> 5;
        s_w[d] = wg[(g * 8 + 2 * m + e) * 36 + tap];
    }

    // ---- stage input tile: warp-per-row, lane-per-column, no div/mod ----
    const float* xb = x + (size_t)b * 4 * 512 * 512;
    #pragma unroll
    for (int cin = 0; cin < 4; cin++) {
        for (int r = wid8; r < 34; r += 8) {
            const int gr = py0 + r;
            const bool rowok = (unsigned)gr < 512u;
            const float* src = xb + ((size_t)cin * 512 + gr) * 512;
            float* dst = &s_in[(cin * 34 + r) * PITCHF];
            const int gc0 = px0 + lane;
            float v0 = 0.f;
            if (rowok && (unsigned)gc0 < 512u) v0 = src[gc0];
            dst[lane] = v0;
            if (lane < 2) {
                const int c1 = 32 + lane;
                const int gc1 = px0 + c1;
                float v1 = 0.f;
                if (rowok && (unsigned)gc1 < 512u) v1 = src[gc1];
                dst[c1] = v1;
            }
        }
    }
    __syncthreads();

    const int m   = tid & 3;
    const int tcx = (tid >> 2) & 3;
    const int ty  = tid >> 4;

    const float* s_wm = s_w + m * 8;   // weight base for this thread's m

    // acc[g][sp]: f32x2 = (out j=0, out j=1) for plane co = 2g + (m>>1),
    // out row 2*(h0+ty) + (m&1), superpixel x = w0 + 4*tcx + sp
    unsigned long long acc[4][4];
    #pragma unroll
    for (int g = 0; g < 4; g++)
        #pragma unroll
        for (int sp = 0; sp < 4; sp++)
            acc[g][sp] = 0ull;

    // apply row `row` to group-half gy (g = 2*gy, 2*gy+1) at tap row ky
    #define APPLY(GY, KY, CIN, ROW)                                         \
    {                                                                       \
        _Pragma("unroll")                                                   \
        for (int kx = 0; kx < 3; kx++) {                                    \
            const float* wb = s_wm + ((CIN) * 9 + (KY) * 3 + kx) * 32       \
                              + (GY) * 4;                                   \
            const ulonglong2 wp = *(const ulonglong2*)(wb);                 \
            _Pragma("unroll")                                               \
            for (int sp = 0; sp < 4; sp++) {                                \
                ffma2(acc[2 * (GY) + 0][sp], wp.x, (ROW)[2 * sp + 0 + kx]); \
                ffma2(acc[2 * (GY) + 1][sp], wp.y, (ROW)[2 * sp + 1 + kx]); \
            }                                                               \
        }                                                                   \
    }

    #pragma unroll
    for (int cin = 0; cin < 4; cin++) {
        const float* rowbase = &s_in[(cin * 34 + 2 * ty) * PITCHF + 8 * tcx];
        unsigned long long row[10];

        ldrowp(row, rowbase);                 // r = 0
        APPLY(0, 0, cin, row)                 //   gy=0, ky=0
        ldrowp(row, rowbase + PITCHF);        // r = 1
        APPLY(0, 1, cin, row)                 //   gy=0, ky=1
        APPLY(1, 0, cin, row)                 //   gy=1, ky=0
        ldrowp(row, rowbase + 2 * PITCHF);    // r = 2
        APPLY(0, 2, cin, row)                 //   gy=0, ky=2
        APPLY(1, 1, cin, row)                 //   gy=1, ky=1
        ldrowp(row, rowbase + 3 * PITCHF);    // r = 3
        APPLY(1, 2, cin, row)                 //   gy=1, ky=2
    }
    #undef APPLY

    // ---- coalesced stores: per g, 8 consecutive px = 2x STG.128 ----
    float* ob = out + (size_t)b * 8 * 512 * 512;
    const int row_y = 2 * (h0 + ty) + (m & 1);
    const int colbase = 2 * w0 + 8 * tcx;
    #pragma unroll
    for (int g = 0; g < 4; g++) {
        const int co = 2 * g + (m >> 1);
        float* orow = ob + ((size_t)co * 512 + row_y) * 512 + colbase;
        ulonglong2 v0; v0.x = acc[g][0]; v0.y = acc[g][1];
        ulonglong2 v1; v1.x = acc[g][2]; v1.y = acc[g][3];
        *(ulonglong2*)(orow) = v0;
        *(ulonglong2*)(orow + 4) = v1;
    }
}

extern "C" void kernel_launch(void* const* d_in, const int* in_sizes, int n_in,
                              void* d_out, int out_size) {
    const float* x = (const float*)d_in[0];   // [8,4,512,512]
    const float* w = (const float*)d_in[1];   // [32,36,1,1]
    float* out = (float*)d_out;               // [8,8,512,512]
    dim3 grid(16, 16, 8);                     // 2048 blocks, 256 thr
    pconv_kernel<<<grid, 256>>>(x, w, out);
}